// round 3
// baseline (speedup 1.0000x reference)
#include <cuda_runtime.h>

// Gate on wires {5,13} of a 26-qubit float32 state.
// Flat index bit for wire w is (25 - w): wire5 -> bit 20, wire13 -> bit 12.
// Compact rest index r (24 bits) expands to full address by inserting 0-bits
// at positions 12 and 20. Four amplitudes per group at +0, +2^12, +2^20,
// +2^20+2^12.  out[t] = sum_s U[t*4+s] * x[s], t = b5*2 + b13.

#define OFF01 4096u          // 2^12  (wire 13 bit)
#define OFF10 1048576u       // 2^20  (wire 5 bit)

__global__ void __launch_bounds__(256)
unitary_gate_kernel(const float* __restrict__ x,
                    const float* __restrict__ U,
                    float* __restrict__ out) {
    unsigned tid = blockIdx.x * blockDim.x + threadIdx.x;
    unsigned r = tid << 2;  // 4 consecutive rest-indices per thread (bits 0..11 free)

    // expand: r bits [0,11] -> addr [0,11]; [12,18] -> [13,19]; [19,23] -> [21,25]
    unsigned a = (r & 0xFFFu) | ((r & 0x7F000u) << 1) | ((r >> 19) << 21);

    const float4 v00 = *reinterpret_cast<const float4*>(x + a);
    const float4 v01 = *reinterpret_cast<const float4*>(x + a + OFF01);
    const float4 v10 = *reinterpret_cast<const float4*>(x + a + OFF10);
    const float4 v11 = *reinterpret_cast<const float4*>(x + a + OFF10 + OFF01);

    const float4 u0 = reinterpret_cast<const float4*>(U)[0];  // row t=0
    const float4 u1 = reinterpret_cast<const float4*>(U)[1];  // row t=1
    const float4 u2 = reinterpret_cast<const float4*>(U)[2];  // row t=2
    const float4 u3 = reinterpret_cast<const float4*>(U)[3];  // row t=3

    float4 o00, o01, o10, o11;
#define APPLY(c) \
    o00.c = u0.x * v00.c + u0.y * v01.c + u0.z * v10.c + u0.w * v11.c; \
    o01.c = u1.x * v00.c + u1.y * v01.c + u1.z * v10.c + u1.w * v11.c; \
    o10.c = u2.x * v00.c + u2.y * v01.c + u2.z * v10.c + u2.w * v11.c; \
    o11.c = u3.x * v00.c + u3.y * v01.c + u3.z * v10.c + u3.w * v11.c;
    APPLY(x) APPLY(y) APPLY(z) APPLY(w)
#undef APPLY

    *reinterpret_cast<float4*>(out + a)                 = o00;
    *reinterpret_cast<float4*>(out + a + OFF01)         = o01;
    *reinterpret_cast<float4*>(out + a + OFF10)         = o10;
    *reinterpret_cast<float4*>(out + a + OFF10 + OFF01) = o11;
}

extern "C" void kernel_launch(void* const* d_in, const int* in_sizes, int n_in,
                              void* d_out, int out_size) {
    const float* x = (const float*)d_in[0];   // 2^26 floats
    const float* U = (const float*)d_in[1];   // 16 floats (4x4 row-major)
    float* out = (float*)d_out;               // 2^26 floats

    // 2^24 rest-groups, 4 per thread -> 2^22 threads
    const int threads = 256;
    const int blocks = (1 << 22) / threads;   // 16384
    unitary_gate_kernel<<<blocks, threads>>>(x, U, out);
}